// round 3
// baseline (speedup 1.0000x reference)
#include <cuda_runtime.h>
#include <cuda_bf16.h>

#define THREADS 256
#define TILE_EDGES 64
#define XPITCH 132                    // fp32 words per staged edge row (pad 4 banks)
#define BUFSZ (TILE_EDGES * XPITCH)   // floats per X buffer

__device__ int g_idx_is64;

static __device__ __forceinline__ unsigned int pack_bf16x2(float lo, float hi) {
    __nv_bfloat162 h = __float22bfloat162_rn(make_float2(lo, hi));
    return *reinterpret_cast<unsigned int*>(&h);
}

// ---------------- prep: zero output + detect index dtype ----------------
__global__ void prep_kernel(float4* out, int n4, const unsigned int* idxw, int n_pairs) {
    int i = blockIdx.x * blockDim.x + threadIdx.x;
    int stride = gridDim.x * blockDim.x;
    for (; i < n4; i += stride) out[i] = make_float4(0.f, 0.f, 0.f, 0.f);
    if (blockIdx.x == 0) {
        __shared__ unsigned int acc;
        if (threadIdx.x == 0) acc = 0u;
        __syncthreads();
        unsigned int v = 0u;
        for (int j = threadIdx.x; j < n_pairs; j += blockDim.x) v |= idxw[2 * j + 1];
        atomicOr(&acc, v);
        __syncthreads();
        if (threadIdx.x == 0) g_idx_is64 = (acc == 0u) ? 1 : 0;
    }
}

// ---------------- fused gate-GEMM + coalesced scatter ----------------
__global__ __launch_bounds__(THREADS, 1)
void fused_gate_scatter(const float* __restrict__ x,
                        const float* __restrict__ Wg,
                        const float* __restrict__ lparam,
                        const void* __restrict__ index,
                        float* __restrict__ out,
                        long long E, int num_tiles)
{
    extern __shared__ char smem_raw[];
    float* Xsm = reinterpret_cast<float*>(smem_raw);                  // 2 x [64][XPITCH]
    long long* Nsm = reinterpret_cast<long long*>(smem_raw + 2 * BUFSZ * 4); // [64]

    const int tid  = threadIdx.x;
    const int wid  = tid >> 5;
    const int lane = tid & 31;
    const int g    = lane >> 2;   // 0..7 : row within warp tile (= local edge)
    const int q    = lane & 3;    // 0..3

    const int   is64 = g_idx_is64;
    const float lp   = fabsf(__ldg(lparam));
    const int   erow = wid * 8 + g;        // this thread's local edge row

    // ---- persistent B fragments in registers: Breg[nt][ks][2] ----
    unsigned int Breg[16][4][2];
    #pragma unroll
    for (int nt = 0; nt < 16; nt++) {
        const int n = nt * 8 + g;
        #pragma unroll
        for (int ks = 0; ks < 4; ks++) {
            const int k = ks * 16 + q * 2;
            float2 w0 = __ldg(reinterpret_cast<const float2*>(Wg + n * 64 + k));
            float2 w1 = __ldg(reinterpret_cast<const float2*>(Wg + n * 64 + k + 8));
            Breg[nt][ks][0] = pack_bf16x2(w0.x, w0.y);
            Breg[nt][ks][1] = pack_bf16x2(w1.x, w1.y);
        }
    }

    const unsigned int smem_base_u32 = (unsigned int)__cvta_generic_to_shared(Xsm);
    const int stride = (int)gridDim.x;

    // stage tile -> buffer via cp.async (16B per op, 8 ops/thread)
    auto stage = [&](int tile, int buf) {
        const long long ebase = (long long)tile * TILE_EDGES;
        #pragma unroll
        for (int p = 0; p < 8; p++) {
            int i  = tid + p * THREADS;   // 0..2047
            int el = i >> 5;
            int jq = i & 31;
            long long e = ebase + el;
            if (e < E) {
                unsigned int dst = smem_base_u32 + (unsigned)((buf * BUFSZ + el * XPITCH + jq * 4) * 4);
                const float* src = x + e * 128 + jq * 4;
                asm volatile("cp.async.cg.shared.global [%0], [%1], 16;" :: "r"(dst), "l"(src));
            }
        }
    };

    int tile = blockIdx.x;
    int buf = 0;
    if (tile < num_tiles) stage(tile, 0);
    asm volatile("cp.async.commit_group;");

    for (; tile < num_tiles; tile += stride) {
        const int nxt = tile + stride;
        if (nxt < num_tiles) stage(nxt, buf ^ 1);
        asm volatile("cp.async.commit_group;");
        asm volatile("cp.async.wait_group 1;");
        __syncthreads();

        const long long ebase = (long long)tile * TILE_EDGES;
        const long long eg = ebase + erow;

        // node id for this edge (one loader per row)
        if (q == 0) {
            long long nd = -1;
            if (eg < E)
                nd = is64 ? reinterpret_cast<const long long*>(index)[eg]
                          : (long long)reinterpret_cast<const int*>(index)[eg];
            Nsm[erow] = nd;
        }

        float* Xrow = Xsm + buf * BUFSZ + erow * XPITCH;

        // ---- MMA: 16 edge-rows (8 edges x 2 patches) x 128 gate cols, K=64 ----
        float acc[16][4];
        #pragma unroll
        for (int nt = 0; nt < 16; nt++) {
            acc[nt][0] = 0.f; acc[nt][1] = 0.f; acc[nt][2] = 0.f; acc[nt][3] = 0.f;
        }

        #pragma unroll
        for (int ks = 0; ks < 4; ks++) {
            const int kb = ks * 16 + q * 2;
            float2 f0 = *reinterpret_cast<const float2*>(Xrow + kb);        // patch0
            float2 f1 = *reinterpret_cast<const float2*>(Xrow + 64 + kb);   // patch1
            float2 f2 = *reinterpret_cast<const float2*>(Xrow + kb + 8);
            float2 f3 = *reinterpret_cast<const float2*>(Xrow + 64 + kb + 8);
            unsigned int a0 = pack_bf16x2(f0.x, f0.y);
            unsigned int a1 = pack_bf16x2(f1.x, f1.y);
            unsigned int a2 = pack_bf16x2(f2.x, f2.y);
            unsigned int a3 = pack_bf16x2(f3.x, f3.y);
            #pragma unroll
            for (int nt = 0; nt < 16; nt++) {
                asm volatile(
                    "mma.sync.aligned.m16n8k16.row.col.f32.bf16.bf16.f32 "
                    "{%0,%1,%2,%3}, {%4,%5,%6,%7}, {%8,%9}, {%0,%1,%2,%3};"
                    : "+f"(acc[nt][0]), "+f"(acc[nt][1]),
                      "+f"(acc[nt][2]), "+f"(acc[nt][3])
                    : "r"(a0), "r"(a1), "r"(a2), "r"(a3),
                      "r"(Breg[nt][ks][0]), "r"(Breg[nt][ks][1]));
            }
        }

        // ---- epilogue: clamp + recombine + in-place write of final values ----
        #pragma unroll
        for (int nt = 0; nt < 8; nt++) {
            const int dlo = nt * 8 + q * 2;
            float2 e0 = *reinterpret_cast<const float2*>(Xrow + dlo);       // patch0 e
            float2 e1 = *reinterpret_cast<const float2*>(Xrow + 64 + dlo);  // patch1 e
            // chunk 0 (output cols dlo, dlo+1): gate cols dlo -> acc[nt]
            float g0x = __saturatef(acc[nt][0]), g0y = __saturatef(acc[nt][1]);
            float g1x = __saturatef(acc[nt][2]), g1y = __saturatef(acc[nt][3]);
            float s0x = e0.x * g0x + e1.x * g1x;
            float s0y = e0.y * g0y + e1.y * g1y;
            // chunk 1 (output cols dlo+64): gate cols dlo+64 -> acc[nt+8]
            float h0x = __saturatef(acc[nt + 8][0]), h0y = __saturatef(acc[nt + 8][1]);
            float h1x = __saturatef(acc[nt + 8][2]), h1y = __saturatef(acc[nt + 8][3]);
            float s1x = e0.x * h0x + e1.x * h1x;
            float s1y = e0.y * h0y + e1.y * h1y;
            float2 w0 = make_float2(fmaf(lp, s0x, e0.x), fmaf(lp, s0y, e0.y));
            float2 w1 = make_float2(fmaf(lp, s1x, e1.x), fmaf(lp, s1y, e1.y));
            *reinterpret_cast<float2*>(Xrow + dlo) = w0;
            *reinterpret_cast<float2*>(Xrow + 64 + dlo) = w1;
        }
        __syncwarp();

        // ---- coalesced scatter: one warp-wide red.v4 per edge (512B/row) ----
        #pragma unroll
        for (int e2 = 0; e2 < 8; e2++) {
            const int row = wid * 8 + e2;
            const long long nd = Nsm[row];
            if (nd >= 0) {
                const float4 v = *reinterpret_cast<const float4*>(
                    Xsm + buf * BUFSZ + row * XPITCH + lane * 4);
                float* p = out + nd * 128 + lane * 4;
                asm volatile("red.global.add.v4.f32 [%0], {%1,%2,%3,%4};"
                             :: "l"(p), "f"(v.x), "f"(v.y), "f"(v.z), "f"(v.w)
                             : "memory");
            }
        }
        __syncthreads();
        buf ^= 1;
    }
}

// ---------------- launch ----------------
extern "C" void kernel_launch(void* const* d_in, const int* in_sizes, int n_in,
                              void* d_out, int out_size) {
    const float* x   = (const float*)d_in[0];
    const float* Wg  = (const float*)d_in[1];
    const float* lp  = (const float*)d_in[2];
    const void*  idx = d_in[3];
    float* out = (float*)d_out;

    long long E = (long long)in_sizes[0] / 128;
    int tiles = (int)((E + TILE_EDGES - 1) / TILE_EDGES);

    int dev = 0; cudaGetDevice(&dev);
    int sms = 148;
    cudaDeviceGetAttribute(&sms, cudaDevAttrMultiProcessorCount, dev);

    // prep: zero output + detect index dtype (single launch)
    int n4 = out_size / 4;
    int npairs = (int)(E / 2); if (npairs > 4096) npairs = 4096;
    int zgrid = (n4 + THREADS - 1) / THREADS;
    prep_kernel<<<zgrid, THREADS>>>((float4*)d_out, n4, (const unsigned int*)idx, npairs);

    size_t smem = (size_t)2 * BUFSZ * 4 + 64 * sizeof(long long);
    cudaFuncSetAttribute(fused_gate_scatter,
                         cudaFuncAttributeMaxDynamicSharedMemorySize, (int)smem);
    int grid = sms;
    if (grid > tiles) grid = tiles;
    fused_gate_scatter<<<grid, THREADS, smem>>>(x, Wg, lp, idx, out, E, tiles);
}

// round 4
// speedup vs baseline: 1.2828x; 1.2828x over previous
#include <cuda_runtime.h>
#include <cuda_bf16.h>

#define THREADS 256
#define TILE 32
#define XPITCH 132                 // fp32 words per staged edge row (4-bank pad)
#define BUFSZ (TILE * XPITCH)      // 4224 floats / buffer
#define NBUF 4
#define OPITCH 132

__device__ int g_idx_is64;

static __device__ __forceinline__ unsigned int pack_bf16x2(float lo, float hi) {
    __nv_bfloat162 hh = __float22bfloat162_rn(make_float2(lo, hi));
    return *reinterpret_cast<unsigned int*>(&hh);
}

// ---------------- prep: zero output + detect index dtype ----------------
__global__ void prep_kernel(float4* out, int n4, const unsigned int* idxw, int n_pairs) {
    int i = blockIdx.x * blockDim.x + threadIdx.x;
    int stride = gridDim.x * blockDim.x;
    for (; i < n4; i += stride) out[i] = make_float4(0.f, 0.f, 0.f, 0.f);
    if (blockIdx.x == 0) {
        __shared__ unsigned int acc;
        if (threadIdx.x == 0) acc = 0u;
        __syncthreads();
        unsigned int v = 0u;
        for (int j = threadIdx.x; j < n_pairs; j += blockDim.x) v |= idxw[2 * j + 1];
        atomicOr(&acc, v);
        __syncthreads();
        if (threadIdx.x == 0) g_idx_is64 = (acc == 0u) ? 1 : 0;
    }
}

// ---------------- fused gate-GEMM + coalesced scatter ----------------
__global__ __launch_bounds__(THREADS, 2)
void fused_gate_scatter(const float* __restrict__ x,
                        const float* __restrict__ Wg,
                        const float* __restrict__ lparam,
                        const void* __restrict__ index,
                        float* __restrict__ out,
                        long long E, int num_tiles)
{
    extern __shared__ char smem_raw[];
    float* Xsm = reinterpret_cast<float*>(smem_raw);          // NBUF x [32][XPITCH]
    float* Osm = Xsm + NBUF * BUFSZ;                          // [32][OPITCH]
    long long* Nsm = reinterpret_cast<long long*>(Osm + TILE * OPITCH); // NBUF x 32
    int* Nsm32 = reinterpret_cast<int*>(Nsm);

    const int tid   = threadIdx.x;
    const int wid   = tid >> 5;
    const int lane  = tid & 31;
    const int g     = lane >> 2;      // 0..7
    const int q     = lane & 3;       // 0..3
    const int group = wid >> 1;       // 0..3 : edge group of 8
    const int h     = wid & 1;        // 0/1  : gate-col half
    const int erow  = group * 8 + g;  // local edge row (0..31)

    const int   is64 = g_idx_is64;
    const float lp   = fabsf(__ldg(lparam));

    // ---- persistent B fragments: cols n = h*64 + nt*8 + g ----
    unsigned int Breg[8][4][2];
    #pragma unroll
    for (int nt = 0; nt < 8; nt++) {
        const int n = h * 64 + nt * 8 + g;
        #pragma unroll
        for (int ks = 0; ks < 4; ks++) {
            const int k = ks * 16 + q * 2;
            float2 w0 = __ldg(reinterpret_cast<const float2*>(Wg + n * 64 + k));
            float2 w1 = __ldg(reinterpret_cast<const float2*>(Wg + n * 64 + k + 8));
            Breg[nt][ks][0] = pack_bf16x2(w0.x, w0.y);
            Breg[nt][ks][1] = pack_bf16x2(w1.x, w1.y);
        }
    }

    const unsigned int xsm_u32 = (unsigned int)__cvta_generic_to_shared(Xsm);
    const unsigned int nsm_u32 = (unsigned int)__cvta_generic_to_shared(Nsm);
    const int S = (int)gridDim.x;

    auto stage = [&](int tile, int slot) {
        const long long ebase = (long long)tile * TILE;
        #pragma unroll
        for (int p = 0; p < 4; p++) {
            int i  = tid + p * THREADS;     // 0..1023
            int el = i >> 5;
            int jq = i & 31;
            long long e = ebase + el;
            if (e < E) {
                unsigned int dst = xsm_u32 + (unsigned)((slot * BUFSZ + el * XPITCH + jq * 4) * 4);
                const float* src = x + e * 128 + jq * 4;
                asm volatile("cp.async.cg.shared.global [%0], [%1], 16;" :: "r"(dst), "l"(src));
            }
        }
        // index staging (same cp.async group)
        if (ebase + TILE <= E) {
            if (is64) {
                if (tid < 16) {
                    unsigned int dst = nsm_u32 + (unsigned)(slot * TILE * 8 + tid * 16);
                    const char* src = (const char*)index + ebase * 8 + tid * 16;
                    asm volatile("cp.async.ca.shared.global [%0], [%1], 16;" :: "r"(dst), "l"(src));
                }
            } else {
                if (tid < 8) {
                    unsigned int dst = nsm_u32 + (unsigned)(slot * TILE * 8 + tid * 16);
                    const char* src = (const char*)index + ebase * 4 + tid * 16;
                    asm volatile("cp.async.ca.shared.global [%0], [%1], 16;" :: "r"(dst), "l"(src));
                }
            }
        } else {  // last (partial) tile: guarded direct loads
            if (tid < TILE) {
                long long e = ebase + tid;
                if (e < E) {
                    if (is64) Nsm[slot * TILE + tid] = ((const long long*)index)[e];
                    else      Nsm32[slot * TILE * 2 + tid] = ((const int*)index)[e];
                }
            }
        }
    };

    // ---- prologue: prime NBUF-1 stages ----
    #pragma unroll
    for (int j = 0; j < NBUF - 1; j++) {
        int t = blockIdx.x + j * S;
        if (t < num_tiles) stage(t, j);
        asm volatile("cp.async.commit_group;");
    }

    int c = 0;
    for (int tcur = blockIdx.x; tcur < num_tiles; tcur += S, c++) {
        __syncthreads();   // everyone done with the slot we're about to overwrite
        int tpre = tcur + (NBUF - 1) * S;
        if (tpre < num_tiles) stage(tpre, (c + NBUF - 1) & (NBUF - 1));
        asm volatile("cp.async.commit_group;");
        asm volatile("cp.async.wait_group %0;" :: "n"(NBUF - 1));
        __syncthreads();   // current slot visible to all warps

        const int slot = c & (NBUF - 1);
        const long long ebase = (long long)tcur * TILE;
        const float* Xrow = Xsm + slot * BUFSZ + erow * XPITCH;

        // ---- MMA: 8 edges x 2 patches (16 rows) x 64 gate cols, K=64 ----
        float acc[8][4];
        #pragma unroll
        for (int nt = 0; nt < 8; nt++) {
            acc[nt][0] = 0.f; acc[nt][1] = 0.f; acc[nt][2] = 0.f; acc[nt][3] = 0.f;
        }

        #pragma unroll
        for (int ks = 0; ks < 4; ks++) {
            const int kb = ks * 16 + q * 2;
            float2 f0 = *reinterpret_cast<const float2*>(Xrow + kb);        // patch0
            float2 f1 = *reinterpret_cast<const float2*>(Xrow + 64 + kb);   // patch1
            float2 f2 = *reinterpret_cast<const float2*>(Xrow + kb + 8);
            float2 f3 = *reinterpret_cast<const float2*>(Xrow + 64 + kb + 8);
            unsigned int a0 = pack_bf16x2(f0.x, f0.y);
            unsigned int a1 = pack_bf16x2(f1.x, f1.y);
            unsigned int a2 = pack_bf16x2(f2.x, f2.y);
            unsigned int a3 = pack_bf16x2(f3.x, f3.y);
            #pragma unroll
            for (int nt = 0; nt < 8; nt++) {
                asm volatile(
                    "mma.sync.aligned.m16n8k16.row.col.f32.bf16.bf16.f32 "
                    "{%0,%1,%2,%3}, {%4,%5,%6,%7}, {%8,%9}, {%0,%1,%2,%3};"
                    : "+f"(acc[nt][0]), "+f"(acc[nt][1]),
                      "+f"(acc[nt][2]), "+f"(acc[nt][3])
                    : "r"(a0), "r"(a1), "r"(a2), "r"(a3),
                      "r"(Breg[nt][ks][0]), "r"(Breg[nt][ks][1]));
            }
        }

        // ---- epilogue: clamp + recombine + pass-through -> Osm (own half) ----
        float* Orow = Osm + erow * OPITCH + h * 64;
        #pragma unroll
        for (int nt = 0; nt < 8; nt++) {
            const int d = nt * 8 + q * 2;   // col within chunk (= patch dim index)
            float2 e0 = *reinterpret_cast<const float2*>(Xrow + d);       // e1[edge,0,d..]
            float2 e1 = *reinterpret_cast<const float2*>(Xrow + 64 + d);  // e1[edge,1,d..]
            float sx = e0.x * __saturatef(acc[nt][0]) + e1.x * __saturatef(acc[nt][2]);
            float sy = e0.y * __saturatef(acc[nt][1]) + e1.y * __saturatef(acc[nt][3]);
            float bx = h ? e1.x : e0.x;     // pass-through e[edge, h*64+d]
            float by = h ? e1.y : e0.y;
            float2 w = make_float2(fmaf(lp, sx, bx), fmaf(lp, sy, by));
            *reinterpret_cast<float2*>(Orow + d) = w;
        }
        __syncwarp();

        // ---- scatter: this warp's 8 edges, its 64-col half; 256B per red row ----
        const int c4 = lane & 15;
        #pragma unroll
        for (int it = 0; it < 4; it++) {
            const int row = group * 8 + it * 2 + (lane >> 4);
            if (ebase + row < E) {
                long long nd = is64 ? Nsm[slot * TILE + row]
                                    : (long long)Nsm32[slot * TILE * 2 + row];
                const float4 v = *reinterpret_cast<const float4*>(
                    Osm + row * OPITCH + h * 64 + c4 * 4);
                float* p = out + nd * 128 + h * 64 + c4 * 4;
                asm volatile("red.global.add.v4.f32 [%0], {%1,%2,%3,%4};"
                             :: "l"(p), "f"(v.x), "f"(v.y), "f"(v.z), "f"(v.w)
                             : "memory");
            }
        }
    }
}

// ---------------- launch ----------------
extern "C" void kernel_launch(void* const* d_in, const int* in_sizes, int n_in,
                              void* d_out, int out_size) {
    const float* x   = (const float*)d_in[0];
    const float* Wg  = (const float*)d_in[1];
    const float* lp  = (const float*)d_in[2];
    const void*  idx = d_in[3];

    long long E = (long long)in_sizes[0] / 128;
    int tiles = (int)((E + TILE - 1) / TILE);

    int dev = 0; cudaGetDevice(&dev);
    int sms = 148;
    cudaDeviceGetAttribute(&sms, cudaDevAttrMultiProcessorCount, dev);

    // prep: zero output + detect index dtype (single launch)
    int n4 = out_size / 4;
    int npairs = (int)(E / 2); if (npairs > 4096) npairs = 4096;
    int zgrid = (n4 + THREADS - 1) / THREADS;
    prep_kernel<<<zgrid, THREADS>>>((float4*)d_out, n4, (const unsigned int*)idx, npairs);

    size_t smem = (size_t)NBUF * BUFSZ * 4      // X buffers
                + (size_t)TILE * OPITCH * 4     // Osm
                + (size_t)NBUF * TILE * 8;      // Nsm
    cudaFuncSetAttribute(fused_gate_scatter,
                         cudaFuncAttributeMaxDynamicSharedMemorySize, (int)smem);
    int grid = 2 * sms;
    if (grid > tiles) grid = tiles;
    fused_gate_scatter<<<grid, THREADS, smem>>>(x, Wg, lp, idx, (float*)d_out, E, tiles);
}

// round 5
// speedup vs baseline: 1.4433x; 1.1252x over previous
#include <cuda_runtime.h>
#include <cuda_bf16.h>

#define THREADS 192
#define TILE 24
#define XPITCH 132                 // fp32 words per staged edge row (4-bank pad)
#define BUFSZ (TILE * XPITCH)      // floats per buffer
#define NBUF 4

__device__ int g_idx_is64;

static __device__ __forceinline__ unsigned int pack_bf16x2(float lo, float hi) {
    __nv_bfloat162 hh = __float22bfloat162_rn(make_float2(lo, hi));
    return *reinterpret_cast<unsigned int*>(&hh);
}

// ---------------- prep: zero output + detect index dtype ----------------
__global__ void prep_kernel(float4* out, int n4, const unsigned int* idxw, int n_pairs) {
    int i = blockIdx.x * blockDim.x + threadIdx.x;
    int stride = gridDim.x * blockDim.x;
    for (; i < n4; i += stride) out[i] = make_float4(0.f, 0.f, 0.f, 0.f);
    if (blockIdx.x == 0) {
        __shared__ unsigned int acc;
        if (threadIdx.x == 0) acc = 0u;
        __syncthreads();
        unsigned int v = 0u;
        for (int j = threadIdx.x; j < n_pairs; j += blockDim.x) v |= idxw[2 * j + 1];
        atomicOr(&acc, v);
        __syncthreads();
        if (threadIdx.x == 0) g_idx_is64 = (acc == 0u) ? 1 : 0;
    }
}

// ---------------- fused gate-GEMM + register scatter ----------------
__global__ __launch_bounds__(THREADS, 2)
void fused_gate_scatter(const float* __restrict__ x,
                        const float* __restrict__ Wg,
                        const float* __restrict__ lparam,
                        const void* __restrict__ index,
                        float* __restrict__ out,
                        long long E, int num_tiles)
{
    extern __shared__ char smem_raw[];
    float* Xsm = reinterpret_cast<float*>(smem_raw);                     // NBUF x [TILE][XPITCH]
    long long* Nsm = reinterpret_cast<long long*>(Xsm + NBUF * BUFSZ);   // NBUF x TILE
    int* Nsm32 = reinterpret_cast<int*>(Nsm);

    const int tid   = threadIdx.x;
    const int wid   = tid >> 5;
    const int lane  = tid & 31;
    const int g     = lane >> 2;      // 0..7
    const int q     = lane & 3;       // 0..3
    const int group = wid >> 1;       // 0..2 : edge group of 8
    const int h     = wid & 1;        // 0/1  : gate-col half
    const int erow  = group * 8 + g;  // local edge row (0..23)

    const int   is64 = g_idx_is64;
    const float lp   = fabsf(__ldg(lparam));

    // ---- persistent B fragments: cols n = h*64 + nt*8 + g ----
    unsigned int Breg[8][4][2];
    #pragma unroll
    for (int nt = 0; nt < 8; nt++) {
        const int n = h * 64 + nt * 8 + g;
        #pragma unroll
        for (int ks = 0; ks < 4; ks++) {
            const int k = ks * 16 + q * 2;
            float2 w0 = __ldg(reinterpret_cast<const float2*>(Wg + n * 64 + k));
            float2 w1 = __ldg(reinterpret_cast<const float2*>(Wg + n * 64 + k + 8));
            Breg[nt][ks][0] = pack_bf16x2(w0.x, w0.y);
            Breg[nt][ks][1] = pack_bf16x2(w1.x, w1.y);
        }
    }

    const unsigned int xsm_u32 = (unsigned int)__cvta_generic_to_shared(Xsm);
    const unsigned int nsm_u32 = (unsigned int)__cvta_generic_to_shared(Nsm);
    const int S = (int)gridDim.x;

    auto stage = [&](int tile, int slot) {
        const long long ebase = (long long)tile * TILE;
        #pragma unroll
        for (int p = 0; p < 4; p++) {
            int i  = tid + p * THREADS;     // 0..767
            int el = i >> 5;
            int jq = i & 31;
            long long e = ebase + el;
            if (e < E) {
                unsigned int dst = xsm_u32 + (unsigned)((slot * BUFSZ + el * XPITCH + jq * 4) * 4);
                const float* src = x + e * 128 + jq * 4;
                asm volatile("cp.async.cg.shared.global [%0], [%1], 16;" :: "r"(dst), "l"(src));
            }
        }
        if (ebase + TILE <= E) {
            if (is64) {
                if (tid < 12) {   // 24 * 8B = 192B
                    unsigned int dst = nsm_u32 + (unsigned)(slot * TILE * 8 + tid * 16);
                    const char* src = (const char*)index + ebase * 8 + tid * 16;
                    asm volatile("cp.async.ca.shared.global [%0], [%1], 16;" :: "r"(dst), "l"(src));
                }
            } else {
                if (tid < 6) {    // 24 * 4B = 96B
                    unsigned int dst = nsm_u32 + (unsigned)(slot * TILE * 8 + tid * 16);
                    const char* src = (const char*)index + ebase * 4 + tid * 16;
                    asm volatile("cp.async.ca.shared.global [%0], [%1], 16;" :: "r"(dst), "l"(src));
                }
            }
        } else {   // partial tail tile: guarded direct loads
            if (tid < TILE) {
                long long e = ebase + tid;
                if (e < E) {
                    if (is64) Nsm[slot * TILE + tid] = ((const long long*)index)[e];
                    else      Nsm32[slot * TILE * 2 + tid] = ((const int*)index)[e];
                }
            }
        }
    };

    // ---- prologue: prime NBUF-1 stages ----
    #pragma unroll
    for (int j = 0; j < NBUF - 1; j++) {
        int t = blockIdx.x + j * S;
        if (t < num_tiles) stage(t, j);
        asm volatile("cp.async.commit_group;");
    }

    int c = 0;
    for (int tcur = blockIdx.x; tcur < num_tiles; tcur += S, c++) {
        __syncthreads();   // all warps done with the slot being restaged
        int tpre = tcur + (NBUF - 1) * S;
        if (tpre < num_tiles) stage(tpre, (c + NBUF - 1) & (NBUF - 1));
        asm volatile("cp.async.commit_group;");
        asm volatile("cp.async.wait_group %0;" :: "n"(NBUF - 1));
        __syncthreads();   // current slot visible

        const int slot = c & (NBUF - 1);
        const long long ebase = (long long)tcur * TILE;
        const bool valid = (ebase + erow < E);
        const float* Xrow = Xsm + slot * BUFSZ + erow * XPITCH;

        // ---- MMA with A-fragments kept for the epilogue ----
        float2 F0[4], F1[4], F2[4], F3[4];
        float acc[8][4];
        #pragma unroll
        for (int nt = 0; nt < 8; nt++) {
            acc[nt][0] = 0.f; acc[nt][1] = 0.f; acc[nt][2] = 0.f; acc[nt][3] = 0.f;
        }

        #pragma unroll
        for (int ks = 0; ks < 4; ks++) {
            const int kb = ks * 16 + q * 2;
            F0[ks] = *reinterpret_cast<const float2*>(Xrow + kb);        // patch0, col kb
            F1[ks] = *reinterpret_cast<const float2*>(Xrow + 64 + kb);   // patch1, col kb
            F2[ks] = *reinterpret_cast<const float2*>(Xrow + kb + 8);    // patch0, col kb+8
            F3[ks] = *reinterpret_cast<const float2*>(Xrow + 64 + kb + 8);
            unsigned int a0 = pack_bf16x2(F0[ks].x, F0[ks].y);
            unsigned int a1 = pack_bf16x2(F1[ks].x, F1[ks].y);
            unsigned int a2 = pack_bf16x2(F2[ks].x, F2[ks].y);
            unsigned int a3 = pack_bf16x2(F3[ks].x, F3[ks].y);
            #pragma unroll
            for (int nt = 0; nt < 8; nt++) {
                asm volatile(
                    "mma.sync.aligned.m16n8k16.row.col.f32.bf16.bf16.f32 "
                    "{%0,%1,%2,%3}, {%4,%5,%6,%7}, {%8,%9}, {%0,%1,%2,%3};"
                    : "+f"(acc[nt][0]), "+f"(acc[nt][1]),
                      "+f"(acc[nt][2]), "+f"(acc[nt][3])
                    : "r"(a0), "r"(a1), "r"(a2), "r"(a3),
                      "r"(Breg[nt][ks][0]), "r"(Breg[nt][ks][1]));
            }
        }

        // ---- epilogue + direct register scatter (no smem round-trip) ----
        long long nd = 0;
        if (valid)
            nd = is64 ? Nsm[slot * TILE + erow]
                      : (long long)Nsm32[slot * TILE * 2 + erow];
        float* pbase = out + nd * 128 + h * 64 + q * 2;

        #pragma unroll
        for (int nt = 0; nt < 8; nt++) {
            const int ks = nt >> 1;
            float2 e0 = (nt & 1) ? F2[ks] : F0[ks];   // patch0 e at col 8*nt+q*2
            float2 e1 = (nt & 1) ? F3[ks] : F1[ks];   // patch1 e
            float sx = e0.x * __saturatef(acc[nt][0]) + e1.x * __saturatef(acc[nt][2]);
            float sy = e0.y * __saturatef(acc[nt][1]) + e1.y * __saturatef(acc[nt][3]);
            float bx = h ? e1.x : e0.x;               // pass-through e[edge, h*64+col]
            float by = h ? e1.y : e0.y;
            float vx = fmaf(lp, sx, bx);
            float vy = fmaf(lp, sy, by);
            if (valid) {
                asm volatile("red.global.add.v2.f32 [%0], {%1, %2};"
                             :: "l"(pbase + nt * 8), "f"(vx), "f"(vy) : "memory");
            }
        }
    }
}

// ---------------- launch ----------------
extern "C" void kernel_launch(void* const* d_in, const int* in_sizes, int n_in,
                              void* d_out, int out_size) {
    const float* x   = (const float*)d_in[0];
    const float* Wg  = (const float*)d_in[1];
    const float* lp  = (const float*)d_in[2];
    const void*  idx = d_in[3];

    long long E = (long long)in_sizes[0] / 128;
    int tiles = (int)((E + TILE - 1) / TILE);

    int dev = 0; cudaGetDevice(&dev);
    int sms = 148;
    cudaDeviceGetAttribute(&sms, cudaDevAttrMultiProcessorCount, dev);

    // prep: zero output + detect index dtype (single launch)
    int n4 = out_size / 4;
    long long npairs64 = E / 2; int npairs = npairs64 > 4096 ? 4096 : (int)npairs64;
    int zgrid = (n4 + 255) / 256;
    prep_kernel<<<zgrid, 256>>>((float4*)d_out, n4, (const unsigned int*)idx, npairs);

    size_t smem = (size_t)NBUF * BUFSZ * 4 + (size_t)NBUF * TILE * 8;
    cudaFuncSetAttribute(fused_gate_scatter,
                         cudaFuncAttributeMaxDynamicSharedMemorySize, (int)smem);
    int grid = 2 * sms;
    if (grid > tiles) grid = tiles;
    fused_gate_scatter<<<grid, THREADS, smem>>>(x, Wg, lp, idx, (float*)d_out, E, tiles);
}

// round 6
// speedup vs baseline: 1.4443x; 1.0007x over previous
#include <cuda_runtime.h>
#include <cuda_bf16.h>

#define THREADS 192
#define TILE 24
#define XPITCH 132                 // fp32 words per staged edge row (4-bank pad)
#define BUFSZ (TILE * XPITCH)      // floats per buffer
#define NBUF 4

__device__ int g_idx_is64;

static __device__ __forceinline__ unsigned int pack_bf16x2(float lo, float hi) {
    __nv_bfloat162 hh = __float22bfloat162_rn(make_float2(lo, hi));
    return *reinterpret_cast<unsigned int*>(&hh);
}

// ---------------- prep: zero output + detect index dtype ----------------
__global__ void prep_kernel(float4* out, int n4, const unsigned int* idxw, int n_pairs) {
    int i = blockIdx.x * blockDim.x + threadIdx.x;
    int stride = gridDim.x * blockDim.x;
    for (; i < n4; i += stride) out[i] = make_float4(0.f, 0.f, 0.f, 0.f);
    if (blockIdx.x == 0) {
        __shared__ unsigned int acc;
        if (threadIdx.x == 0) acc = 0u;
        __syncthreads();
        unsigned int v = 0u;
        for (int j = threadIdx.x; j < n_pairs; j += blockDim.x) v |= idxw[2 * j + 1];
        atomicOr(&acc, v);
        __syncthreads();
        if (threadIdx.x == 0) g_idx_is64 = (acc == 0u) ? 1 : 0;
    }
}

// ---------------- fused gate-GEMM + register scatter ----------------
__global__ __launch_bounds__(THREADS, 2)
void fused_gate_scatter(const float* __restrict__ x,
                        const float* __restrict__ Wg,
                        const float* __restrict__ lparam,
                        const void* __restrict__ index,
                        float* __restrict__ out,
                        long long E, int num_tiles)
{
    extern __shared__ char smem_raw[];
    float* Xsm = reinterpret_cast<float*>(smem_raw);                     // NBUF x [TILE][XPITCH]
    long long* Nsm = reinterpret_cast<long long*>(Xsm + NBUF * BUFSZ);   // NBUF x TILE
    int* Nsm32 = reinterpret_cast<int*>(Nsm);

    const int tid   = threadIdx.x;
    const int wid   = tid >> 5;
    const int lane  = tid & 31;
    const int g     = lane >> 2;      // 0..7
    const int q     = lane & 3;       // 0..3
    const int group = wid >> 1;       // 0..2 : edge group of 8
    const int h     = wid & 1;        // 0/1  : gate-col half
    const int erow  = group * 8 + g;  // local edge row (0..23)

    const int   is64 = g_idx_is64;
    const float lp   = fabsf(__ldg(lparam));

    // ---- persistent B fragments: cols n = h*64 + nt*8 + g ----
    unsigned int Breg[8][4][2];
    #pragma unroll
    for (int nt = 0; nt < 8; nt++) {
        const int n = h * 64 + nt * 8 + g;
        #pragma unroll
        for (int ks = 0; ks < 4; ks++) {
            const int k = ks * 16 + q * 2;
            float2 w0 = __ldg(reinterpret_cast<const float2*>(Wg + n * 64 + k));
            float2 w1 = __ldg(reinterpret_cast<const float2*>(Wg + n * 64 + k + 8));
            Breg[nt][ks][0] = pack_bf16x2(w0.x, w0.y);
            Breg[nt][ks][1] = pack_bf16x2(w1.x, w1.y);
        }
    }

    const unsigned int xsm_u32 = (unsigned int)__cvta_generic_to_shared(Xsm);
    const unsigned int nsm_u32 = (unsigned int)__cvta_generic_to_shared(Nsm);
    const int S = (int)gridDim.x;

    auto stage = [&](int tile, int slot) {
        const long long ebase = (long long)tile * TILE;
        #pragma unroll
        for (int p = 0; p < 4; p++) {
            int i  = tid + p * THREADS;     // 0..767
            int el = i >> 5;
            int jq = i & 31;
            long long e = ebase + el;
            if (e < E) {
                unsigned int dst = xsm_u32 + (unsigned)((slot * BUFSZ + el * XPITCH + jq * 4) * 4);
                const float* src = x + e * 128 + jq * 4;
                asm volatile("cp.async.cg.shared.global [%0], [%1], 16;" :: "r"(dst), "l"(src));
            }
        }
        if (ebase + TILE <= E) {
            if (is64) {
                if (tid < 12) {   // 24 * 8B = 192B
                    unsigned int dst = nsm_u32 + (unsigned)(slot * TILE * 8 + tid * 16);
                    const char* src = (const char*)index + ebase * 8 + tid * 16;
                    asm volatile("cp.async.ca.shared.global [%0], [%1], 16;" :: "r"(dst), "l"(src));
                }
            } else {
                if (tid < 6) {    // 24 * 4B = 96B
                    unsigned int dst = nsm_u32 + (unsigned)(slot * TILE * 8 + tid * 16);
                    const char* src = (const char*)index + ebase * 4 + tid * 16;
                    asm volatile("cp.async.ca.shared.global [%0], [%1], 16;" :: "r"(dst), "l"(src));
                }
            }
        } else {   // partial tail tile: guarded direct loads
            if (tid < TILE) {
                long long e = ebase + tid;
                if (e < E) {
                    if (is64) Nsm[slot * TILE + tid] = ((const long long*)index)[e];
                    else      Nsm32[slot * TILE * 2 + tid] = ((const int*)index)[e];
                }
            }
        }
    };

    // ---- prologue: prime NBUF-1 stages ----
    #pragma unroll
    for (int j = 0; j < NBUF - 1; j++) {
        int t = blockIdx.x + j * S;
        if (t < num_tiles) stage(t, j);
        asm volatile("cp.async.commit_group;");
    }

    int c = 0;
    for (int tcur = blockIdx.x; tcur < num_tiles; tcur += S, c++) {
        __syncthreads();   // all warps done with the slot being restaged
        int tpre = tcur + (NBUF - 1) * S;
        if (tpre < num_tiles) stage(tpre, (c + NBUF - 1) & (NBUF - 1));
        asm volatile("cp.async.commit_group;");
        asm volatile("cp.async.wait_group %0;" :: "n"(NBUF - 1));
        __syncthreads();   // current slot visible

        const int slot = c & (NBUF - 1);
        const long long ebase = (long long)tcur * TILE;
        const bool valid = (ebase + erow < E);
        const float* Xrow = Xsm + slot * BUFSZ + erow * XPITCH;

        // ---- MMA with A-fragments kept for the epilogue ----
        float2 F0[4], F1[4], F2[4], F3[4];
        float acc[8][4];
        #pragma unroll
        for (int nt = 0; nt < 8; nt++) {
            acc[nt][0] = 0.f; acc[nt][1] = 0.f; acc[nt][2] = 0.f; acc[nt][3] = 0.f;
        }

        #pragma unroll
        for (int ks = 0; ks < 4; ks++) {
            const int kb = ks * 16 + q * 2;
            F0[ks] = *reinterpret_cast<const float2*>(Xrow + kb);        // patch0, col kb
            F1[ks] = *reinterpret_cast<const float2*>(Xrow + 64 + kb);   // patch1, col kb
            F2[ks] = *reinterpret_cast<const float2*>(Xrow + kb + 8);    // patch0, col kb+8
            F3[ks] = *reinterpret_cast<const float2*>(Xrow + 64 + kb + 8);
            unsigned int a0 = pack_bf16x2(F0[ks].x, F0[ks].y);
            unsigned int a1 = pack_bf16x2(F1[ks].x, F1[ks].y);
            unsigned int a2 = pack_bf16x2(F2[ks].x, F2[ks].y);
            unsigned int a3 = pack_bf16x2(F3[ks].x, F3[ks].y);
            #pragma unroll
            for (int nt = 0; nt < 8; nt++) {
                asm volatile(
                    "mma.sync.aligned.m16n8k16.row.col.f32.bf16.bf16.f32 "
                    "{%0,%1,%2,%3}, {%4,%5,%6,%7}, {%8,%9}, {%0,%1,%2,%3};"
                    : "+f"(acc[nt][0]), "+f"(acc[nt][1]),
                      "+f"(acc[nt][2]), "+f"(acc[nt][3])
                    : "r"(a0), "r"(a1), "r"(a2), "r"(a3),
                      "r"(Breg[nt][ks][0]), "r"(Breg[nt][ks][1]));
            }
        }

        // ---- epilogue + direct register scatter (no smem round-trip) ----
        long long nd = 0;
        if (valid)
            nd = is64 ? Nsm[slot * TILE + erow]
                      : (long long)Nsm32[slot * TILE * 2 + erow];
        float* pbase = out + nd * 128 + h * 64 + q * 2;

        #pragma unroll
        for (int nt = 0; nt < 8; nt++) {
            const int ks = nt >> 1;
            float2 e0 = (nt & 1) ? F2[ks] : F0[ks];   // patch0 e at col 8*nt+q*2
            float2 e1 = (nt & 1) ? F3[ks] : F1[ks];   // patch1 e
            float sx = e0.x * __saturatef(acc[nt][0]) + e1.x * __saturatef(acc[nt][2]);
            float sy = e0.y * __saturatef(acc[nt][1]) + e1.y * __saturatef(acc[nt][3]);
            float bx = h ? e1.x : e0.x;               // pass-through e[edge, h*64+col]
            float by = h ? e1.y : e0.y;
            float vx = fmaf(lp, sx, bx);
            float vy = fmaf(lp, sy, by);
            if (valid) {
                asm volatile("red.global.add.v2.f32 [%0], {%1, %2};"
                             :: "l"(pbase + nt * 8), "f"(vx), "f"(vy) : "memory");
            }
        }
    }
}

// ---------------- launch ----------------
extern "C" void kernel_launch(void* const* d_in, const int* in_sizes, int n_in,
                              void* d_out, int out_size) {
    const float* x   = (const float*)d_in[0];
    const float* Wg  = (const float*)d_in[1];
    const float* lp  = (const float*)d_in[2];
    const void*  idx = d_in[3];

    long long E = (long long)in_sizes[0] / 128;
    int tiles = (int)((E + TILE - 1) / TILE);

    int dev = 0; cudaGetDevice(&dev);
    int sms = 148;
    cudaDeviceGetAttribute(&sms, cudaDevAttrMultiProcessorCount, dev);

    // prep: zero output + detect index dtype (single launch)
    int n4 = out_size / 4;
    long long npairs64 = E / 2; int npairs = npairs64 > 4096 ? 4096 : (int)npairs64;
    int zgrid = (n4 + 255) / 256;
    prep_kernel<<<zgrid, 256>>>((float4*)d_out, n4, (const unsigned int*)idx, npairs);

    size_t smem = (size_t)NBUF * BUFSZ * 4 + (size_t)NBUF * TILE * 8;
    cudaFuncSetAttribute(fused_gate_scatter,
                         cudaFuncAttributeMaxDynamicSharedMemorySize, (int)smem);
    int grid = 2 * sms;
    if (grid > tiles) grid = tiles;
    fused_gate_scatter<<<grid, THREADS, smem>>>(x, Wg, lp, idx, (float*)d_out, E, tiles);
}

// round 7
// speedup vs baseline: 1.5313x; 1.0602x over previous
#include <cuda_runtime.h>
#include <cuda_bf16.h>

#define THREADS 192
#define ROWS 8                        // edges per pair-tile
#define XPITCH 132                    // fp32 words per staged edge row (4-bank pad)
#define SLOT (ROWS * XPITCH)          // floats per slot (1056)
#define NBUF 4

__device__ int g_idx_is64;

static __device__ __forceinline__ unsigned int pack_bf16x2(float lo, float hi) {
    __nv_bfloat162 hh = __float22bfloat162_rn(make_float2(lo, hi));
    return *reinterpret_cast<unsigned int*>(&hh);
}

// ---------------- prep: zero output + detect index dtype ----------------
__global__ void prep_kernel(float4* out, int n4, const unsigned int* idxw, int n_pairs) {
    int i = blockIdx.x * blockDim.x + threadIdx.x;
    int stride = gridDim.x * blockDim.x;
    for (; i < n4; i += stride) out[i] = make_float4(0.f, 0.f, 0.f, 0.f);
    if (blockIdx.x == 0) {
        __shared__ unsigned int acc;
        if (threadIdx.x == 0) acc = 0u;
        __syncthreads();
        unsigned int v = 0u;
        for (int j = threadIdx.x; j < n_pairs; j += blockDim.x) v |= idxw[2 * j + 1];
        atomicOr(&acc, v);
        __syncthreads();
        if (threadIdx.x == 0) g_idx_is64 = (acc == 0u) ? 1 : 0;
    }
}

// ---------------- fused gate-GEMM + register scatter, warp-pair pipelines ----------------
__global__ __launch_bounds__(THREADS, 2)
void fused_gate_scatter(const float* __restrict__ x,
                        const float* __restrict__ Wg,
                        const float* __restrict__ lparam,
                        const void* __restrict__ index,
                        float* __restrict__ out,
                        long long E, int num_tiles)
{
    extern __shared__ char smem_raw[];
    float* Xsm = reinterpret_cast<float*>(smem_raw);                 // [3][NBUF][ROWS][XPITCH]
    long long* Nsm = reinterpret_cast<long long*>(Xsm + 3 * NBUF * SLOT); // [3][NBUF][ROWS]

    const int tid  = threadIdx.x;
    const int wid  = tid >> 5;
    const int lane = tid & 31;
    const int g    = lane >> 2;      // 0..7 : edge row within pair-tile
    const int q    = lane & 3;       // 0..3
    const int pair = wid >> 1;       // 0..2
    const int h    = wid & 1;        // 0/1 : gate-col half

    const int   is64 = g_idx_is64;
    const float lp   = fabsf(__ldg(lparam));

    float* pairBuf = Xsm + pair * (NBUF * SLOT);
    long long* NsmP = Nsm + pair * (NBUF * ROWS);
    int* NsmP32 = reinterpret_cast<int*>(NsmP);

    // ---- persistent B fragments: cols n = h*64 + nt*8 + g ----
    unsigned int Breg[8][4][2];
    #pragma unroll
    for (int nt = 0; nt < 8; nt++) {
        const int n = h * 64 + nt * 8 + g;
        #pragma unroll
        for (int ks = 0; ks < 4; ks++) {
            const int k = ks * 16 + q * 2;
            float2 w0 = __ldg(reinterpret_cast<const float2*>(Wg + n * 64 + k));
            float2 w1 = __ldg(reinterpret_cast<const float2*>(Wg + n * 64 + k + 8));
            Breg[nt][ks][0] = pack_bf16x2(w0.x, w0.y);
            Breg[nt][ks][1] = pack_bf16x2(w1.x, w1.y);
        }
    }

    const unsigned int xbuf_u32 = (unsigned int)__cvta_generic_to_shared(pairBuf);
    const unsigned int nbuf_u32 = (unsigned int)__cvta_generic_to_shared(NsmP);

    // stage one 8-edge tile-let into slot; warp h stages rows h*4 .. h*4+3
    auto stage = [&](int t, int slot) {
        const long long ebase = (long long)t * ROWS;
        #pragma unroll
        for (int p = 0; p < 4; p++) {
            const int row = h * 4 + p;
            long long e = ebase + row;
            if (e < E) {
                unsigned int dst = xbuf_u32 + (unsigned)((slot * SLOT + row * XPITCH + lane * 4) * 4);
                const float* src = x + e * 128 + lane * 4;
                asm volatile("cp.async.cg.shared.global [%0], [%1], 16;" :: "r"(dst), "l"(src));
            }
        }
        if (h == 0) {
            if (ebase + ROWS <= E) {
                if (is64) {
                    if (lane < 4) {   // 8 * 8B = 64B
                        unsigned int dst = nbuf_u32 + (unsigned)(slot * 64 + lane * 16);
                        const char* src = (const char*)index + ebase * 8 + lane * 16;
                        asm volatile("cp.async.ca.shared.global [%0], [%1], 16;" :: "r"(dst), "l"(src));
                    }
                } else {
                    if (lane < 2) {   // 8 * 4B = 32B
                        unsigned int dst = nbuf_u32 + (unsigned)(slot * 64 + lane * 16);
                        const char* src = (const char*)index + ebase * 4 + lane * 16;
                        asm volatile("cp.async.ca.shared.global [%0], [%1], 16;" :: "r"(dst), "l"(src));
                    }
                }
            } else {  // partial tail tile-let: guarded direct loads
                if (lane < ROWS && ebase + lane < E) {
                    if (is64) NsmP[slot * ROWS + lane] = ((const long long*)index)[ebase + lane];
                    else      NsmP32[slot * ROWS * 2 + lane] = ((const int*)index)[ebase + lane];
                }
            }
        }
    };

    const int S = (int)gridDim.x * 3;
    const int pg = (int)blockIdx.x * 3 + pair;

    // ---- prologue: prime 3 slots ----
    #pragma unroll
    for (int j = 0; j < NBUF - 1; j++) {
        int t = pg + j * S;
        if (t < num_tiles) stage(t, j);
        asm volatile("cp.async.commit_group;");
    }

    int c = 0;
    for (int tcur = pg; tcur < num_tiles; tcur += S, c++) {
        asm volatile("cp.async.wait_group %0;" :: "n"(NBUF - 2));   // own slot c complete
        asm volatile("bar.sync %0, 64;" :: "r"(pair + 1) : "memory"); // partner too; restage target free
        int tpre = tcur + (NBUF - 1) * S;
        if (tpre < num_tiles) stage(tpre, (c + NBUF - 1) & (NBUF - 1));
        asm volatile("cp.async.commit_group;");

        const int slot = c & (NBUF - 1);
        const long long ebase = (long long)tcur * ROWS;
        const bool valid = (ebase + g < E);
        const float* Xrow = pairBuf + slot * SLOT + g * XPITCH;

        long long nd = 0;
        if (valid)
            nd = is64 ? NsmP[slot * ROWS + g]
                      : (long long)NsmP32[slot * ROWS * 2 + g];

        // ---- MMA with A-fragments kept for the epilogue ----
        float2 F0[4], F1[4], F2[4], F3[4];
        float acc[8][4];
        #pragma unroll
        for (int nt = 0; nt < 8; nt++) {
            acc[nt][0] = 0.f; acc[nt][1] = 0.f; acc[nt][2] = 0.f; acc[nt][3] = 0.f;
        }

        #pragma unroll
        for (int ks = 0; ks < 4; ks++) {
            const int kb = ks * 16 + q * 2;
            F0[ks] = *reinterpret_cast<const float2*>(Xrow + kb);          // patch0, col kb
            F1[ks] = *reinterpret_cast<const float2*>(Xrow + 64 + kb);     // patch1, col kb
            F2[ks] = *reinterpret_cast<const float2*>(Xrow + kb + 8);      // patch0, col kb+8
            F3[ks] = *reinterpret_cast<const float2*>(Xrow + 64 + kb + 8); // patch1, col kb+8
            unsigned int a0 = pack_bf16x2(F0[ks].x, F0[ks].y);
            unsigned int a1 = pack_bf16x2(F1[ks].x, F1[ks].y);
            unsigned int a2 = pack_bf16x2(F2[ks].x, F2[ks].y);
            unsigned int a3 = pack_bf16x2(F3[ks].x, F3[ks].y);
            #pragma unroll
            for (int nt = 0; nt < 8; nt++) {
                asm volatile(
                    "mma.sync.aligned.m16n8k16.row.col.f32.bf16.bf16.f32 "
                    "{%0,%1,%2,%3}, {%4,%5,%6,%7}, {%8,%9}, {%0,%1,%2,%3};"
                    : "+f"(acc[nt][0]), "+f"(acc[nt][1]),
                      "+f"(acc[nt][2]), "+f"(acc[nt][3])
                    : "r"(a0), "r"(a1), "r"(a2), "r"(a3),
                      "r"(Breg[nt][ks][0]), "r"(Breg[nt][ks][1]));
            }
        }

        // ---- epilogue + direct register scatter ----
        float* pbase = out + nd * 128 + h * 64 + q * 2;
        #pragma unroll
        for (int nt = 0; nt < 8; nt++) {
            const int ks = nt >> 1;
            float2 e0 = (nt & 1) ? F2[ks] : F0[ks];   // patch0 e at col 8*nt+q*2
            float2 e1 = (nt & 1) ? F3[ks] : F1[ks];   // patch1 e
            float sx = e0.x * __saturatef(acc[nt][0]) + e1.x * __saturatef(acc[nt][2]);
            float sy = e0.y * __saturatef(acc[nt][1]) + e1.y * __saturatef(acc[nt][3]);
            float bx = h ? e1.x : e0.x;               // pass-through e[edge, h*64+col]
            float by = h ? e1.y : e0.y;
            float vx = fmaf(lp, sx, bx);
            float vy = fmaf(lp, sy, by);
            if (valid) {
                asm volatile("red.global.add.v2.f32 [%0], {%1, %2};"
                             :: "l"(pbase + nt * 8), "f"(vx), "f"(vy) : "memory");
            }
        }
    }
}

// ---------------- launch ----------------
extern "C" void kernel_launch(void* const* d_in, const int* in_sizes, int n_in,
                              void* d_out, int out_size) {
    const float* x   = (const float*)d_in[0];
    const float* Wg  = (const float*)d_in[1];
    const float* lp  = (const float*)d_in[2];
    const void*  idx = d_in[3];

    long long E = (long long)in_sizes[0] / 128;
    int tiles = (int)((E + ROWS - 1) / ROWS);

    int dev = 0; cudaGetDevice(&dev);
    int sms = 148;
    cudaDeviceGetAttribute(&sms, cudaDevAttrMultiProcessorCount, dev);

    // prep: zero output + detect index dtype (single launch)
    int n4 = out_size / 4;
    long long npairs64 = E / 2; int npairs = npairs64 > 4096 ? 4096 : (int)npairs64;
    int zgrid = (n4 + 255) / 256;
    prep_kernel<<<zgrid, 256>>>((float4*)d_out, n4, (const unsigned int*)idx, npairs);

    size_t smem = (size_t)3 * NBUF * SLOT * 4       // X rings (3 pairs)
                + (size_t)3 * NBUF * ROWS * 8;      // node rings
    cudaFuncSetAttribute(fused_gate_scatter,
                         cudaFuncAttributeMaxDynamicSharedMemorySize, (int)smem);
    int grid = 2 * sms;
    int maxg = (tiles + 2) / 3;
    if (grid > maxg) grid = maxg;
    fused_gate_scatter<<<grid, THREADS, smem>>>(x, Wg, lp, idx, (float*)d_out, E, tiles);
}